// round 14
// baseline (speedup 1.0000x reference)
#include <cuda_runtime.h>
#include <cuda_fp16.h>
#include <cstdint>

#define NB 4
#define SEQ 4096
#define DIM 1024
#define NH 16
#define HDIM 64
#define WINS 512
#define NWIN 8
#define NGT 128

// ---------------- scratch (static device globals; no allocation) ----------------
__device__ __half g_xph[NB * SEQ * DIM];     // x + pos_emb (fp16)
__device__ __half g_local[NB * SEQ * DIM];   // local attention out
__device__ __half g_glob[NB * SEQ * DIM];    // global attention out
__device__ __half g_mixed[NB * SEQ * DIM];   // gated mix
__device__ __half g_gth[NB * NGT * DIM];     // [comp ; global_memory] per batch (fp16)
__device__ __half g_gwT[DIM * 2 * DIM];      // gate_w transposed [1024][2048]
__device__ __half g_owT[DIM * DIM];          // out_w transposed  [1024][1024]
__device__ __half g_cwT[DIM * 4096];         // conv_w rearranged [dout][ktap*1024+din]
__device__ float g_comp[256 * DIM];          // conv split-K accumulator (fp32)

// ---------------- helpers ----------------
__device__ __forceinline__ uint32_t pack2(float a, float b) {
    __half2 h = __floats2half2_rn(a, b);
    return *(uint32_t*)&h;
}
__device__ __forceinline__ uint32_t smem_u32(const void* p) {
    uint32_t a;
    asm("{ .reg .u64 t; cvta.to.shared.u64 t, %1; cvt.u32.u64 %0, t; }"
        : "=r"(a) : "l"(p));
    return a;
}
__device__ __forceinline__ void cp_async16(uint32_t dst, const void* src) {
    asm volatile("cp.async.cg.shared.global [%0], [%1], 16;"
                 :: "r"(dst), "l"(__cvta_generic_to_global(src)) : "memory");
}
__device__ __forceinline__ void cp_commit() {
    asm volatile("cp.async.commit_group;" ::: "memory");
}

__device__ __forceinline__ void ldsm_x4(uint32_t& r0, uint32_t& r1, uint32_t& r2,
                                        uint32_t& r3, uint32_t addr) {
    asm volatile("ldmatrix.sync.aligned.m8n8.x4.shared.b16 {%0,%1,%2,%3}, [%4];"
                 : "=r"(r0), "=r"(r1), "=r"(r2), "=r"(r3) : "r"(addr));
}
__device__ __forceinline__ void ldsm_x4_t(uint32_t& r0, uint32_t& r1, uint32_t& r2,
                                          uint32_t& r3, uint32_t addr) {
    asm volatile("ldmatrix.sync.aligned.m8n8.x4.trans.shared.b16 {%0,%1,%2,%3}, [%4];"
                 : "=r"(r0), "=r"(r1), "=r"(r2), "=r"(r3) : "r"(addr));
}

// fast exp on fma/alu pipes (no MUFU). |rel err| ~2e-6.
__device__ __forceinline__ float fexp(float x) {
    float z = fmaxf(x, -87.3365f) * 1.4426950408889634f;
    float s = z + 12582912.0f;
    int n = __float_as_int(s) - 0x4b400000;
    float f = z - (s - 12582912.0f);
    float p = 1.3371542e-3f;
    p = fmaf(p, f, 9.6181291e-3f);
    p = fmaf(p, f, 5.5504109e-2f);
    p = fmaf(p, f, 2.4022651e-1f);
    p = fmaf(p, f, 6.9314718e-1f);
    p = fmaf(p, f, 1.0f);
    return __int_as_float(__float_as_int(p) + (n << 23));
}

// 2^z on fma/alu pipes (input already in log2 domain)
__device__ __forceinline__ float fexp2(float z) {
    z = fmaxf(z, -126.0f);
    float s = z + 12582912.0f;
    int n = __float_as_int(s) - 0x4b400000;
    float f = z - (s - 12582912.0f);
    float p = 1.3371542e-3f;
    p = fmaf(p, f, 9.6181291e-3f);
    p = fmaf(p, f, 5.5504109e-2f);
    p = fmaf(p, f, 2.4022651e-1f);
    p = fmaf(p, f, 6.9314718e-1f);
    p = fmaf(p, f, 1.0f);
    return __int_as_float(__float_as_int(p) + (n << 23));
}

// fp16 mma with fp32 accum: D = A(16x16) B(16x8) + D
__device__ __forceinline__ void mma_f16(float* c, uint32_t a0, uint32_t a1,
                                        uint32_t a2, uint32_t a3,
                                        uint32_t b0, uint32_t b1) {
    asm volatile(
        "mma.sync.aligned.m16n8k16.row.col.f32.f16.f16.f32 "
        "{%0,%1,%2,%3}, {%4,%5,%6,%7}, {%8,%9}, {%0,%1,%2,%3};"
        : "+f"(c[0]), "+f"(c[1]), "+f"(c[2]), "+f"(c[3])
        : "r"(a0), "r"(a1), "r"(a2), "r"(a3), "r"(b0), "r"(b1));
}

#define LDH32(arr, idx) (*(const uint32_t*)((arr) + (idx)))

// ================ fused prep: add_pos | transpose gw | transpose ow |
//                  cw_rearrange | zero_comp (blockIdx-partitioned) ================
#define PREP_AP 16384
#define PREP_T1 (PREP_AP + 2048)
#define PREP_T2 (PREP_T1 + 1024)
#define PREP_CW (PREP_T2 + 4096)
#define PREP_END (PREP_CW + 256)

__global__ __launch_bounds__(256) void prep_kernel(const float* __restrict__ x,
                                                   const float* __restrict__ pe,
                                                   const float* __restrict__ gw,
                                                   const float* __restrict__ ow,
                                                   const float* __restrict__ cw) {
    __shared__ float t[32][33];
    int bx = blockIdx.x;
    int tid = threadIdx.x;
    if (bx < PREP_AP) {
        int i = bx * 256 + tid;
        float4 a = ((const float4*)x)[i];
        float4 p = ((const float4*)pe)[i & 1048575];
        ((uint2*)g_xph)[i] = make_uint2(pack2(a.x + p.x, a.y + p.y),
                                        pack2(a.z + p.z, a.w + p.w));
    } else if (bx < PREP_T2) {
        const float* in;
        __half* out;
        int K, idx;
        if (bx < PREP_T1) {
            idx = bx - PREP_AP; in = gw; K = 2048;
            __half* p2; asm("mov.u64 %0, g_gwT;" : "=l"(p2)); out = p2;
        } else {
            idx = bx - PREP_T1; in = ow; K = 1024;
            __half* p2; asm("mov.u64 %0, g_owT;" : "=l"(p2)); out = p2;
        }
        int bxn = (idx & 31) * 32;
        int by = (idx >> 5) * 32;
        int xx = tid & 31, yy = tid >> 5;
#pragma unroll
        for (int i = 0; i < 32; i += 8)
            t[yy + i][xx] = in[(by + yy + i) * 1024 + bxn + xx];
        __syncthreads();
#pragma unroll
        for (int i = 0; i < 32; i += 8)
            out[(bxn + yy + i) * K + by + xx] = __float2half_rn(t[xx][yy + i]);
    } else if (bx < PREP_CW) {
        int i = (bx - PREP_T2) * 256 + tid;
        int dout = i >> 10, q = i & 1023;
        int c4 = q << 2;
        int ktap = c4 >> 10, din = c4 & 1023;
        const float* base = cw + dout * 4096 + din * 4 + ktap;
        *(uint2*)(g_cwT + dout * 4096 + c4) =
            make_uint2(pack2(base[0], base[4]), pack2(base[8], base[12]));
    } else {
        int i = (bx - PREP_CW) * 256 + tid;
        ((float4*)g_comp)[i] = make_float4(0.f, 0.f, 0.f, 0.f);
    }
}

// ---------------- conv scatter + gt fill (merged) ----------------
__global__ __launch_bounds__(256) void scatter_gt_kernel(const float* __restrict__ cb,
                                                         const float* __restrict__ gm) {
    int bx = blockIdx.x;
    int tid = threadIdx.x;
    if (bx < 256) {
        int i = bx * 256 + tid;
        int r = i >> 8, c4 = (i & 255) << 2;
        float4 v = *(const float4*)(g_comp + r * 1024 + c4);
        float4 b = *(const float4*)(cb + c4);
        int outr = ((r >> 6) << 7) | (r & 63);
        *(uint2*)(g_gth + outr * 1024 + c4) =
            make_uint2(pack2(v.x + b.x, v.y + b.y), pack2(v.z + b.z, v.w + b.w));
    } else {
        int i = (bx - 256) * 256 + tid;
        float4 v = ((const float4*)gm)[i & 16383];
        *(uint2*)(g_gth + (i >> 14) * 131072 + 65536 + (i & 16383) * 4) =
            make_uint2(pack2(v.x, v.y), pack2(v.z, v.w));
    }
}

// ===== fp16 flash attention: ldmatrix + register P + 3-deep cp.async K pipeline =====
// smem: 3 x Ks[64][72] halves = 27648 B; Q staged in first 18432 B first.
// Q pre-scaled by 0.125*log2(e); softmax in log2 domain via fexp2.
#define KT_BYTES 9216
__device__ __forceinline__ void flash_mma(const __half* __restrict__ qb,
                                          const __half* __restrict__ kb,
                                          __half* __restrict__ obp, int nkt) {
    extern __shared__ __half smh[];
    const uint32_t smbase = smem_u32(smh);
    const int tid = threadIdx.x;
    const int warp = tid >> 5, lane = tid & 31;
    const int g = lane >> 2, tg = lane & 3;
    const int wm = warp * 16;

    // stage Q scaled by 0.125*log2e
    const __half2 sc2 = __float2half2_rn(0.125f * 1.4426950408889634f);
#pragma unroll
    for (int it = 0; it < 4; ++it) {
        int f = tid + it * 256;
        int row = f >> 3, c8 = (f & 7) << 3;
        uint4 v = *(const uint4*)(qb + row * DIM + c8);
        __half2* hv = (__half2*)&v;
#pragma unroll
        for (int j = 0; j < 4; ++j) hv[j] = __hmul2(hv[j], sc2);
        *(uint4*)(smh + row * 72 + c8) = v;
    }
    __syncthreads();

    uint32_t qf[4][4];
#pragma unroll
    for (int ks = 0; ks < 4; ++ks) {
        int row = wm + (lane & 7) + ((lane >> 3) & 1) * 8;
        int col = ks * 16 + (lane >> 4) * 8;
        ldsm_x4(qf[ks][0], qf[ks][1], qf[ks][2], qf[ks][3],
                smbase + (row * 72 + col) * 2);
    }
    __syncthreads();

    // prologue: prefetch up to 2 K tiles
#pragma unroll
    for (int p = 0; p < 2; ++p) {
        if (p < nkt) {
            const uint32_t dst = smbase + p * KT_BYTES;
            const __half* kbp = kb + p * 64 * DIM;
#pragma unroll
            for (int it = 0; it < 2; ++it) {
                int f = tid + it * 256;
                int row = f >> 3, c8 = (f & 7) << 3;
                cp_async16(dst + (row * 72 + c8) * 2, kbp + row * DIM + c8);
            }
            cp_commit();
        }
    }

    float m0 = -1e30f, m1 = -1e30f, l0 = 0.f, l1 = 0.f;
    float oacc[8][4];
#pragma unroll
    for (int j = 0; j < 8; ++j)
#pragma unroll
        for (int q = 0; q < 4; ++q) oacc[j][q] = 0.f;

    int cb3 = 0;  // kt % 3
    for (int kt = 0; kt < nkt; ++kt) {
        if (kt + 1 < nkt)
            asm volatile("cp.async.wait_group 1;" ::: "memory");
        else
            asm volatile("cp.async.wait_group 0;" ::: "memory");
        __syncthreads();
        const uint32_t cur = smbase + cb3 * KT_BYTES;

        // prefetch tile kt+2
        if (kt + 2 < nkt) {
            int nb = cb3 + 2; if (nb >= 3) nb -= 3;
            const uint32_t nxt = smbase + nb * KT_BYTES;
            const __half* kbn = kb + (kt + 2) * 64 * DIM;
#pragma unroll
            for (int it = 0; it < 2; ++it) {
                int f = tid + it * 256;
                int row = f >> 3, c8 = (f & 7) << 3;
                cp_async16(nxt + (row * 72 + c8) * 2, kbn + row * DIM + c8);
            }
            cp_commit();
        }

        // ---- S = Q K^T (log2 domain) ----
        float sacc[8][4];
#pragma unroll
        for (int j = 0; j < 8; ++j)
#pragma unroll
            for (int q = 0; q < 4; ++q) sacc[j][q] = 0.f;
#pragma unroll
        for (int j = 0; j < 8; ++j) {
#pragma unroll
            for (int kp = 0; kp < 2; ++kp) {
                int row = j * 8 + (lane & 7);
                int col = kp * 32 + (lane >> 3) * 8;
                uint32_t b0, b1, b2, b3;
                ldsm_x4(b0, b1, b2, b3, cur + (row * 72 + col) * 2);
                mma_f16(sacc[j], qf[2 * kp][0], qf[2 * kp][1], qf[2 * kp][2],
                        qf[2 * kp][3], b0, b1);
                mma_f16(sacc[j], qf[2 * kp + 1][0], qf[2 * kp + 1][1],
                        qf[2 * kp + 1][2], qf[2 * kp + 1][3], b2, b3);
            }
        }

        // ---- online softmax, base-2 ----
        float mx0 = -1e30f, mx1 = -1e30f;
#pragma unroll
        for (int j = 0; j < 8; ++j) {
            mx0 = fmaxf(mx0, fmaxf(sacc[j][0], sacc[j][1]));
            mx1 = fmaxf(mx1, fmaxf(sacc[j][2], sacc[j][3]));
        }
        mx0 = fmaxf(mx0, __shfl_xor_sync(0xffffffffu, mx0, 1));
        mx0 = fmaxf(mx0, __shfl_xor_sync(0xffffffffu, mx0, 2));
        mx1 = fmaxf(mx1, __shfl_xor_sync(0xffffffffu, mx1, 1));
        mx1 = fmaxf(mx1, __shfl_xor_sync(0xffffffffu, mx1, 2));
        float mn0 = fmaxf(m0, mx0), mn1 = fmaxf(m1, mx1);
        float c0 = fexp2(m0 - mn0), c1 = fexp2(m1 - mn1);
        m0 = mn0; m1 = mn1;
        float s0 = 0.f, s1 = 0.f;
#pragma unroll
        for (int j = 0; j < 8; ++j) {
            sacc[j][0] = fexp2(sacc[j][0] - mn0);
            sacc[j][1] = fexp2(sacc[j][1] - mn0);
            sacc[j][2] = fexp2(sacc[j][2] - mn1);
            sacc[j][3] = fexp2(sacc[j][3] - mn1);
            s0 += sacc[j][0] + sacc[j][1];
            s1 += sacc[j][2] + sacc[j][3];
        }
        s0 += __shfl_xor_sync(0xffffffffu, s0, 1);
        s0 += __shfl_xor_sync(0xffffffffu, s0, 2);
        s1 += __shfl_xor_sync(0xffffffffu, s1, 1);
        s1 += __shfl_xor_sync(0xffffffffu, s1, 2);
        l0 = l0 * c0 + s0;
        l1 = l1 * c1 + s1;
#pragma unroll
        for (int j = 0; j < 8; ++j) {
            oacc[j][0] *= c0; oacc[j][1] *= c0;
            oacc[j][2] *= c1; oacc[j][3] *= c1;
        }

        // ---- O += P V ----
#pragma unroll
        for (int ks = 0; ks < 4; ++ks) {
            uint32_t pa0 = pack2(sacc[2 * ks][0], sacc[2 * ks][1]);
            uint32_t pa1 = pack2(sacc[2 * ks][2], sacc[2 * ks][3]);
            uint32_t pa2 = pack2(sacc[2 * ks + 1][0], sacc[2 * ks + 1][1]);
            uint32_t pa3 = pack2(sacc[2 * ks + 1][2], sacc[2 * ks + 1][3]);
#pragma unroll
            for (int j2 = 0; j2 < 4; ++j2) {
                int row = ks * 16 + (lane & 15);
                int col = j2 * 16 + (lane >> 4) * 8;
                uint32_t b0, b1, b2, b3;
                ldsm_x4_t(b0, b1, b2, b3, cur + (row * 72 + col) * 2);
                mma_f16(oacc[2 * j2], pa0, pa1, pa2, pa3, b0, b1);
                mma_f16(oacc[2 * j2 + 1], pa0, pa1, pa2, pa3, b2, b3);
            }
        }
        if (++cb3 == 3) cb3 = 0;
    }

    float inv0 = 1.0f / l0, inv1 = 1.0f / l1;
#pragma unroll
    for (int j = 0; j < 8; ++j) {
        int cb = j * 8 + 2 * tg;
        *(uint32_t*)(obp + (wm + g) * DIM + cb) =
            pack2(oacc[j][0] * inv0, oacc[j][1] * inv0);
        *(uint32_t*)(obp + (wm + g + 8) * DIM + cb) =
            pack2(oacc[j][2] * inv1, oacc[j][3] * inv1);
    }
}

// merged attention: blocks [0,2048) local, [2048,4096) global
__global__ __launch_bounds__(256, 2) void attn_kernel() {
    int bx = blockIdx.x;
    if (bx < 2048) {
        int qt = bx & 3;
        int h = (bx >> 2) & 15;
        int w = (bx >> 6) & 7;
        int b = bx >> 9;
        const __half* base = g_xph + (b * SEQ + w * WINS) * DIM + h * HDIM;
        const __half* qb = base + (qt * 128) * DIM;
        __half* ob = g_local + (b * SEQ + w * WINS + qt * 128) * DIM + h * HDIM;
        flash_mma(qb, base, ob, 8);
    } else {
        bx -= 2048;
        int qt = bx & 31;
        int h = (bx >> 5) & 15;
        int b = bx >> 9;
        const __half* qb = g_xph + (b * SEQ + qt * 128) * DIM + h * HDIM;
        const __half* kb = g_gth + b * NGT * DIM + h * HDIM;
        __half* ob = g_glob + (b * SEQ + qt * 128) * DIM + h * HDIM;
        flash_mma(qb, kb, ob, 2);
    }
}

// ============== pipelined fp16 mma GEMM, 128x128 tile, KT=32 halves ==============
// (scalar-LDS fragments — the R9 configuration, which benchmarked fastest)
#define STG_H 10240
#define GP_SMEM (2 * STG_H * 2)

template <int MODE>
__device__ __forceinline__ void gp_load(__half* sm, int s, int m0, int n0, int k0,
                                        const __half* Bsrc, int tid) {
    __half* A = sm + s * STG_H;
    __half* B = A + 5120;
    constexpr int KTOT = (MODE == 0) ? 4096 : (MODE == 1) ? 2048 : 1024;
#pragma unroll
    for (int t = 0; t < 2; ++t) {
        int id = tid + t * 256;
        int r = id >> 2, q = id & 3;
        int kk = k0 + q * 8;
        const __half* src;
        if (MODE == 0) {
            int row = m0 + r;
            src = g_xph + ((row >> 6) * SEQ + (row & 63) * 4) * DIM + kk;
        } else if (MODE == 1) {
            src = (kk < 1024) ? g_local + (m0 + r) * 1024 + kk
                              : g_glob + (m0 + r) * 1024 + (kk - 1024);
        } else {
            src = g_mixed + (m0 + r) * 1024 + kk;
        }
        cp_async16(smem_u32(A + r * 40 + q * 8), src);
    }
#pragma unroll
    for (int t = 0; t < 2; ++t) {
        int id = tid + t * 256;
        int r = id >> 2, q = id & 3;
        cp_async16(smem_u32(B + r * 40 + q * 8), Bsrc + (n0 + r) * KTOT + k0 + q * 8);
    }
    cp_commit();
}

template <int MODE>
__global__ __launch_bounds__(256) void gemm_pipe(const float* __restrict__ bias,
                                                 float* __restrict__ Cext) {
    constexpr int NIT = (MODE == 0) ? 16 : (MODE == 1) ? 64 : 32;
    extern __shared__ __half smh[];
    const int tid = threadIdx.x;
    const int warp = tid >> 5, lane = tid & 31;
    const int g = lane >> 2, tg = lane & 3;
    const int wm = (warp >> 1) * 32, wn = (warp & 1) * 64;
    const int m0 = blockIdx.y * 128, n0 = blockIdx.x * 128;
    const int kbase = (MODE == 0) ? blockIdx.z * 512 : 0;
    const __half* Bsrc = (MODE == 0) ? g_cwT : (MODE == 1) ? g_gwT : g_owT;

    float acc[2][8][4];
#pragma unroll
    for (int mt = 0; mt < 2; ++mt)
#pragma unroll
        for (int j = 0; j < 8; ++j)
#pragma unroll
            for (int q = 0; q < 4; ++q) acc[mt][j][q] = 0.f;

    gp_load<MODE>(smh, 0, m0, n0, kbase, Bsrc, tid);

    for (int i = 0; i < NIT; ++i) {
        if (i + 1 < NIT) {
            gp_load<MODE>(smh, (i + 1) & 1, m0, n0, kbase + (i + 1) * 32, Bsrc, tid);
            asm volatile("cp.async.wait_group 1;" ::: "memory");
        } else {
            asm volatile("cp.async.wait_group 0;" ::: "memory");
        }
        __syncthreads();

        const __half* As = smh + (i & 1) * STG_H;
        const __half* Bs = As + 5120;
#pragma unroll
        for (int ks = 0; ks < 2; ++ks) {
            uint32_t bf[8][2];
#pragma unroll
            for (int j = 0; j < 8; ++j) {
                int n = wn + j * 8 + g;
                bf[j][0] = LDH32(Bs, n * 40 + ks * 16 + 2 * tg);
                bf[j][1] = LDH32(Bs, n * 40 + ks * 16 + 2 * tg + 8);
            }
#pragma unroll
            for (int mt = 0; mt < 2; ++mt) {
                int r0 = wm + mt * 16 + g;
                uint32_t a0 = LDH32(As, r0 * 40 + ks * 16 + 2 * tg);
                uint32_t a1 = LDH32(As, (r0 + 8) * 40 + ks * 16 + 2 * tg);
                uint32_t a2 = LDH32(As, r0 * 40 + ks * 16 + 2 * tg + 8);
                uint32_t a3 = LDH32(As, (r0 + 8) * 40 + ks * 16 + 2 * tg + 8);
#pragma unroll
                for (int j = 0; j < 8; ++j)
                    mma_f16(acc[mt][j], a0, a1, a2, a3, bf[j][0], bf[j][1]);
            }
        }
        __syncthreads();
    }

    // ---- epilogue ----
#pragma unroll
    for (int mt = 0; mt < 2; ++mt) {
#pragma unroll
        for (int j = 0; j < 8; ++j) {
            int col = n0 + wn + j * 8 + 2 * tg;
            int ra = m0 + wm + mt * 16 + g;
            int rb = ra + 8;
            if (MODE == 0) {
                atomicAdd(&g_comp[ra * 1024 + col], acc[mt][j][0]);
                atomicAdd(&g_comp[ra * 1024 + col + 1], acc[mt][j][1]);
                atomicAdd(&g_comp[rb * 1024 + col], acc[mt][j][2]);
                atomicAdd(&g_comp[rb * 1024 + col + 1], acc[mt][j][3]);
                continue;
            }
            float2 bz = *(const float2*)&bias[col];
            float z0x = acc[mt][j][0] + bz.x, z0y = acc[mt][j][1] + bz.y;
            float z1x = acc[mt][j][2] + bz.x, z1y = acc[mt][j][3] + bz.y;
            if (MODE == 1) {
                int ia = ra * 1024 + col, ib = rb * 1024 + col;
                float2 la = __half22float2(*(const __half2*)(g_local + ia));
                float2 lb = __half22float2(*(const __half2*)(g_local + ib));
                float2 ga = __half22float2(*(const __half2*)(g_glob + ia));
                float2 gb = __half22float2(*(const __half2*)(g_glob + ib));
                float s0x = 1.0f / (1.0f + fexp(-z0x));
                float s0y = 1.0f / (1.0f + fexp(-z0y));
                float s1x = 1.0f / (1.0f + fexp(-z1x));
                float s1y = 1.0f / (1.0f + fexp(-z1y));
                *(uint32_t*)(g_mixed + ia) =
                    pack2(s0x * la.x + (1.f - s0x) * ga.x,
                          s0y * la.y + (1.f - s0y) * ga.y);
                *(uint32_t*)(g_mixed + ib) =
                    pack2(s1x * lb.x + (1.f - s1x) * gb.x,
                          s1y * lb.y + (1.f - s1y) * gb.y);
            } else {
                *(float2*)&Cext[ra * 1024 + col] = make_float2(z0x, z0y);
                *(float2*)&Cext[rb * 1024 + col] = make_float2(z1x, z1y);
            }
        }
    }
}

// ---------------- launch ----------------
extern "C" void kernel_launch(void* const* d_in, const int* in_sizes, int n_in,
                              void* d_out, int out_size) {
    const float* x = (const float*)d_in[0];
    const float* pe = (const float*)d_in[1];
    const float* gm = (const float*)d_in[2];
    const float* cw = (const float*)d_in[3];
    const float* cb = (const float*)d_in[4];
    const float* gw = (const float*)d_in[5];
    const float* gb = (const float*)d_in[6];
    const float* ow = (const float*)d_in[7];
    const float* ob = (const float*)d_in[8];
    float* out = (float*)d_out;

    cudaFuncSetAttribute((const void*)attn_kernel,
                         cudaFuncAttributeMaxDynamicSharedMemorySize, 27648);
    cudaFuncSetAttribute((const void*)gemm_pipe<0>,
                         cudaFuncAttributeMaxDynamicSharedMemorySize, GP_SMEM);
    cudaFuncSetAttribute((const void*)gemm_pipe<1>,
                         cudaFuncAttributeMaxDynamicSharedMemorySize, GP_SMEM);
    cudaFuncSetAttribute((const void*)gemm_pipe<2>,
                         cudaFuncAttributeMaxDynamicSharedMemorySize, GP_SMEM);

    prep_kernel<<<PREP_END, 256>>>(x, pe, gw, ow, cw);
    gemm_pipe<0><<<dim3(8, 2, 8), 256, GP_SMEM>>>(nullptr, nullptr);  // conv split-K
    scatter_gt_kernel<<<512, 256>>>(cb, gm);
    attn_kernel<<<4096, 256, 27648>>>();
    gemm_pipe<1><<<dim3(8, 128), 256, GP_SMEM>>>(gb, nullptr);  // gate + mix
    gemm_pipe<2><<<dim3(8, 128), 256, GP_SMEM>>>(ob, out);      // output projection
}

// round 15
// speedup vs baseline: 1.0033x; 1.0033x over previous
#include <cuda_runtime.h>
#include <cuda_fp16.h>
#include <cstdint>

#define NB 4
#define SEQ 4096
#define DIM 1024
#define NH 16
#define HDIM 64
#define WINS 512
#define NWIN 8
#define NGT 128

// ---------------- scratch (static device globals; no allocation) ----------------
__device__ __half g_xph[NB * SEQ * DIM];     // x + pos_emb (fp16)
__device__ __half g_local[NB * SEQ * DIM];   // local attention out
__device__ __half g_glob[NB * SEQ * DIM];    // global attention out
__device__ __half g_mixed[NB * SEQ * DIM];   // gated mix
__device__ __half g_gth[NB * NGT * DIM];     // [comp ; global_memory] per batch (fp16)
__device__ __half g_gwT[DIM * 2 * DIM];      // gate_w transposed [1024][2048]
__device__ __half g_owT[DIM * DIM];          // out_w transposed  [1024][1024]
__device__ __half g_cwT[DIM * 4096];         // conv_w rearranged [dout][ktap*1024+din]
__device__ float g_comp[256 * DIM];          // conv split-K accumulator (fp32)

// ---------------- helpers ----------------
__device__ __forceinline__ uint32_t pack2(float a, float b) {
    __half2 h = __floats2half2_rn(a, b);
    return *(uint32_t*)&h;
}
__device__ __forceinline__ uint32_t smem_u32(const void* p) {
    uint32_t a;
    asm("{ .reg .u64 t; cvta.to.shared.u64 t, %1; cvt.u32.u64 %0, t; }"
        : "=r"(a) : "l"(p));
    return a;
}
__device__ __forceinline__ void cp_async16(uint32_t dst, const void* src) {
    asm volatile("cp.async.cg.shared.global [%0], [%1], 16;"
                 :: "r"(dst), "l"(__cvta_generic_to_global(src)) : "memory");
}
__device__ __forceinline__ void cp_commit() {
    asm volatile("cp.async.commit_group;" ::: "memory");
}

__device__ __forceinline__ void ldsm_x4(uint32_t& r0, uint32_t& r1, uint32_t& r2,
                                        uint32_t& r3, uint32_t addr) {
    asm volatile("ldmatrix.sync.aligned.m8n8.x4.shared.b16 {%0,%1,%2,%3}, [%4];"
                 : "=r"(r0), "=r"(r1), "=r"(r2), "=r"(r3) : "r"(addr));
}
__device__ __forceinline__ void ldsm_x4_t(uint32_t& r0, uint32_t& r1, uint32_t& r2,
                                          uint32_t& r3, uint32_t addr) {
    asm volatile("ldmatrix.sync.aligned.m8n8.x4.trans.shared.b16 {%0,%1,%2,%3}, [%4];"
                 : "=r"(r0), "=r"(r1), "=r"(r2), "=r"(r3) : "r"(addr));
}

// fast exp on fma/alu pipes (no MUFU). |rel err| ~2e-6.
__device__ __forceinline__ float fexp(float x) {
    float z = fmaxf(x, -87.3365f) * 1.4426950408889634f;
    float s = z + 12582912.0f;
    int n = __float_as_int(s) - 0x4b400000;
    float f = z - (s - 12582912.0f);
    float p = 1.3371542e-3f;
    p = fmaf(p, f, 9.6181291e-3f);
    p = fmaf(p, f, 5.5504109e-2f);
    p = fmaf(p, f, 2.4022651e-1f);
    p = fmaf(p, f, 6.9314718e-1f);
    p = fmaf(p, f, 1.0f);
    return __int_as_float(__float_as_int(p) + (n << 23));
}

// 2^z on fma/alu pipes (input already in log2 domain)
__device__ __forceinline__ float fexp2(float z) {
    z = fmaxf(z, -126.0f);
    float s = z + 12582912.0f;
    int n = __float_as_int(s) - 0x4b400000;
    float f = z - (s - 12582912.0f);
    float p = 1.3371542e-3f;
    p = fmaf(p, f, 9.6181291e-3f);
    p = fmaf(p, f, 5.5504109e-2f);
    p = fmaf(p, f, 2.4022651e-1f);
    p = fmaf(p, f, 6.9314718e-1f);
    p = fmaf(p, f, 1.0f);
    return __int_as_float(__float_as_int(p) + (n << 23));
}

// fp16 mma with fp32 accum: D = A(16x16) B(16x8) + D
__device__ __forceinline__ void mma_f16(float* c, uint32_t a0, uint32_t a1,
                                        uint32_t a2, uint32_t a3,
                                        uint32_t b0, uint32_t b1) {
    asm volatile(
        "mma.sync.aligned.m16n8k16.row.col.f32.f16.f16.f32 "
        "{%0,%1,%2,%3}, {%4,%5,%6,%7}, {%8,%9}, {%0,%1,%2,%3};"
        : "+f"(c[0]), "+f"(c[1]), "+f"(c[2]), "+f"(c[3])
        : "r"(a0), "r"(a1), "r"(a2), "r"(a3), "r"(b0), "r"(b1));
}

#define LDH32(arr, idx) (*(const uint32_t*)((arr) + (idx)))

// ================ fused prep: add_pos | transpose gw | transpose ow |
//                  cw_rearrange | zero_comp (blockIdx-partitioned) ================
#define PREP_AP 16384
#define PREP_T1 (PREP_AP + 2048)
#define PREP_T2 (PREP_T1 + 1024)
#define PREP_CW (PREP_T2 + 4096)
#define PREP_END (PREP_CW + 256)

__global__ __launch_bounds__(256) void prep_kernel(const float* __restrict__ x,
                                                   const float* __restrict__ pe,
                                                   const float* __restrict__ gw,
                                                   const float* __restrict__ ow,
                                                   const float* __restrict__ cw) {
    __shared__ float t[32][33];
    int bx = blockIdx.x;
    int tid = threadIdx.x;
    if (bx < PREP_AP) {
        int i = bx * 256 + tid;
        float4 a = ((const float4*)x)[i];
        float4 p = ((const float4*)pe)[i & 1048575];
        ((uint2*)g_xph)[i] = make_uint2(pack2(a.x + p.x, a.y + p.y),
                                        pack2(a.z + p.z, a.w + p.w));
    } else if (bx < PREP_T2) {
        const float* in;
        __half* out;
        int K, idx;
        if (bx < PREP_T1) {
            idx = bx - PREP_AP; in = gw; K = 2048;
            __half* p2; asm("mov.u64 %0, g_gwT;" : "=l"(p2)); out = p2;
        } else {
            idx = bx - PREP_T1; in = ow; K = 1024;
            __half* p2; asm("mov.u64 %0, g_owT;" : "=l"(p2)); out = p2;
        }
        int bxn = (idx & 31) * 32;
        int by = (idx >> 5) * 32;
        int xx = tid & 31, yy = tid >> 5;
#pragma unroll
        for (int i = 0; i < 32; i += 8)
            t[yy + i][xx] = in[(by + yy + i) * 1024 + bxn + xx];
        __syncthreads();
#pragma unroll
        for (int i = 0; i < 32; i += 8)
            out[(bxn + yy + i) * K + by + xx] = __float2half_rn(t[xx][yy + i]);
    } else if (bx < PREP_CW) {
        int i = (bx - PREP_T2) * 256 + tid;
        int dout = i >> 10, q = i & 1023;
        int c4 = q << 2;
        int ktap = c4 >> 10, din = c4 & 1023;
        const float* base = cw + dout * 4096 + din * 4 + ktap;
        *(uint2*)(g_cwT + dout * 4096 + c4) =
            make_uint2(pack2(base[0], base[4]), pack2(base[8], base[12]));
    } else {
        int i = (bx - PREP_CW) * 256 + tid;
        ((float4*)g_comp)[i] = make_float4(0.f, 0.f, 0.f, 0.f);
    }
}

// ---------------- conv scatter + gt fill (merged) ----------------
__global__ __launch_bounds__(256) void scatter_gt_kernel(const float* __restrict__ cb,
                                                         const float* __restrict__ gm) {
    int bx = blockIdx.x;
    int tid = threadIdx.x;
    if (bx < 256) {
        int i = bx * 256 + tid;
        int r = i >> 8, c4 = (i & 255) << 2;
        float4 v = *(const float4*)(g_comp + r * 1024 + c4);
        float4 b = *(const float4*)(cb + c4);
        int outr = ((r >> 6) << 7) | (r & 63);
        *(uint2*)(g_gth + outr * 1024 + c4) =
            make_uint2(pack2(v.x + b.x, v.y + b.y), pack2(v.z + b.z, v.w + b.w));
    } else {
        int i = (bx - 256) * 256 + tid;
        float4 v = ((const float4*)gm)[i & 16383];
        *(uint2*)(g_gth + (i >> 14) * 131072 + 65536 + (i & 16383) * 4) =
            make_uint2(pack2(v.x, v.y), pack2(v.z, v.w));
    }
}

// ===== fp16 flash attention: ldmatrix + register P + 3-deep cp.async K pipeline =====
// smem: 3 x Ks[64][72] halves = 27648 B; Q staged in first 18432 B first.
// Q pre-scaled by 0.125*log2(e); softmax in log2 domain via fexp2.
#define KT_BYTES 9216
__device__ __forceinline__ void flash_mma(const __half* __restrict__ qb,
                                          const __half* __restrict__ kb,
                                          __half* __restrict__ obp, int nkt) {
    extern __shared__ __half smh[];
    const uint32_t smbase = smem_u32(smh);
    const int tid = threadIdx.x;
    const int warp = tid >> 5, lane = tid & 31;
    const int g = lane >> 2, tg = lane & 3;
    const int wm = warp * 16;

    // stage Q scaled by 0.125*log2e
    const __half2 sc2 = __float2half2_rn(0.125f * 1.4426950408889634f);
#pragma unroll
    for (int it = 0; it < 4; ++it) {
        int f = tid + it * 256;
        int row = f >> 3, c8 = (f & 7) << 3;
        uint4 v = *(const uint4*)(qb + row * DIM + c8);
        __half2* hv = (__half2*)&v;
#pragma unroll
        for (int j = 0; j < 4; ++j) hv[j] = __hmul2(hv[j], sc2);
        *(uint4*)(smh + row * 72 + c8) = v;
    }
    __syncthreads();

    uint32_t qf[4][4];
#pragma unroll
    for (int ks = 0; ks < 4; ++ks) {
        int row = wm + (lane & 7) + ((lane >> 3) & 1) * 8;
        int col = ks * 16 + (lane >> 4) * 8;
        ldsm_x4(qf[ks][0], qf[ks][1], qf[ks][2], qf[ks][3],
                smbase + (row * 72 + col) * 2);
    }
    __syncthreads();

    // prologue: prefetch up to 2 K tiles
#pragma unroll
    for (int p = 0; p < 2; ++p) {
        if (p < nkt) {
            const uint32_t dst = smbase + p * KT_BYTES;
            const __half* kbp = kb + p * 64 * DIM;
#pragma unroll
            for (int it = 0; it < 2; ++it) {
                int f = tid + it * 256;
                int row = f >> 3, c8 = (f & 7) << 3;
                cp_async16(dst + (row * 72 + c8) * 2, kbp + row * DIM + c8);
            }
            cp_commit();
        }
    }

    float m0 = -1e30f, m1 = -1e30f, l0 = 0.f, l1 = 0.f;
    float oacc[8][4];
#pragma unroll
    for (int j = 0; j < 8; ++j)
#pragma unroll
        for (int q = 0; q < 4; ++q) oacc[j][q] = 0.f;

    int cb3 = 0;  // kt % 3
    for (int kt = 0; kt < nkt; ++kt) {
        if (kt + 1 < nkt)
            asm volatile("cp.async.wait_group 1;" ::: "memory");
        else
            asm volatile("cp.async.wait_group 0;" ::: "memory");
        __syncthreads();
        const uint32_t cur = smbase + cb3 * KT_BYTES;

        // prefetch tile kt+2
        if (kt + 2 < nkt) {
            int nb = cb3 + 2; if (nb >= 3) nb -= 3;
            const uint32_t nxt = smbase + nb * KT_BYTES;
            const __half* kbn = kb + (kt + 2) * 64 * DIM;
#pragma unroll
            for (int it = 0; it < 2; ++it) {
                int f = tid + it * 256;
                int row = f >> 3, c8 = (f & 7) << 3;
                cp_async16(nxt + (row * 72 + c8) * 2, kbn + row * DIM + c8);
            }
            cp_commit();
        }

        // ---- S = Q K^T (log2 domain) ----
        float sacc[8][4];
#pragma unroll
        for (int j = 0; j < 8; ++j)
#pragma unroll
            for (int q = 0; q < 4; ++q) sacc[j][q] = 0.f;
#pragma unroll
        for (int j = 0; j < 8; ++j) {
#pragma unroll
            for (int kp = 0; kp < 2; ++kp) {
                int row = j * 8 + (lane & 7);
                int col = kp * 32 + (lane >> 3) * 8;
                uint32_t b0, b1, b2, b3;
                ldsm_x4(b0, b1, b2, b3, cur + (row * 72 + col) * 2);
                mma_f16(sacc[j], qf[2 * kp][0], qf[2 * kp][1], qf[2 * kp][2],
                        qf[2 * kp][3], b0, b1);
                mma_f16(sacc[j], qf[2 * kp + 1][0], qf[2 * kp + 1][1],
                        qf[2 * kp + 1][2], qf[2 * kp + 1][3], b2, b3);
            }
        }

        // ---- online softmax, base-2 ----
        float mx0 = -1e30f, mx1 = -1e30f;
#pragma unroll
        for (int j = 0; j < 8; ++j) {
            mx0 = fmaxf(mx0, fmaxf(sacc[j][0], sacc[j][1]));
            mx1 = fmaxf(mx1, fmaxf(sacc[j][2], sacc[j][3]));
        }
        mx0 = fmaxf(mx0, __shfl_xor_sync(0xffffffffu, mx0, 1));
        mx0 = fmaxf(mx0, __shfl_xor_sync(0xffffffffu, mx0, 2));
        mx1 = fmaxf(mx1, __shfl_xor_sync(0xffffffffu, mx1, 1));
        mx1 = fmaxf(mx1, __shfl_xor_sync(0xffffffffu, mx1, 2));
        float mn0 = fmaxf(m0, mx0), mn1 = fmaxf(m1, mx1);
        float c0 = fexp2(m0 - mn0), c1 = fexp2(m1 - mn1);
        m0 = mn0; m1 = mn1;
        float s0 = 0.f, s1 = 0.f;
#pragma unroll
        for (int j = 0; j < 8; ++j) {
            sacc[j][0] = fexp2(sacc[j][0] - mn0);
            sacc[j][1] = fexp2(sacc[j][1] - mn0);
            sacc[j][2] = fexp2(sacc[j][2] - mn1);
            sacc[j][3] = fexp2(sacc[j][3] - mn1);
            s0 += sacc[j][0] + sacc[j][1];
            s1 += sacc[j][2] + sacc[j][3];
        }
        s0 += __shfl_xor_sync(0xffffffffu, s0, 1);
        s0 += __shfl_xor_sync(0xffffffffu, s0, 2);
        s1 += __shfl_xor_sync(0xffffffffu, s1, 1);
        s1 += __shfl_xor_sync(0xffffffffu, s1, 2);
        l0 = l0 * c0 + s0;
        l1 = l1 * c1 + s1;
#pragma unroll
        for (int j = 0; j < 8; ++j) {
            oacc[j][0] *= c0; oacc[j][1] *= c0;
            oacc[j][2] *= c1; oacc[j][3] *= c1;
        }

        // ---- O += P V ----
#pragma unroll
        for (int ks = 0; ks < 4; ++ks) {
            uint32_t pa0 = pack2(sacc[2 * ks][0], sacc[2 * ks][1]);
            uint32_t pa1 = pack2(sacc[2 * ks][2], sacc[2 * ks][3]);
            uint32_t pa2 = pack2(sacc[2 * ks + 1][0], sacc[2 * ks + 1][1]);
            uint32_t pa3 = pack2(sacc[2 * ks + 1][2], sacc[2 * ks + 1][3]);
#pragma unroll
            for (int j2 = 0; j2 < 4; ++j2) {
                int row = ks * 16 + (lane & 15);
                int col = j2 * 16 + (lane >> 4) * 8;
                uint32_t b0, b1, b2, b3;
                ldsm_x4_t(b0, b1, b2, b3, cur + (row * 72 + col) * 2);
                mma_f16(oacc[2 * j2], pa0, pa1, pa2, pa3, b0, b1);
                mma_f16(oacc[2 * j2 + 1], pa0, pa1, pa2, pa3, b2, b3);
            }
        }
        if (++cb3 == 3) cb3 = 0;
    }

    float inv0 = 1.0f / l0, inv1 = 1.0f / l1;
#pragma unroll
    for (int j = 0; j < 8; ++j) {
        int cb = j * 8 + 2 * tg;
        *(uint32_t*)(obp + (wm + g) * DIM + cb) =
            pack2(oacc[j][0] * inv0, oacc[j][1] * inv0);
        *(uint32_t*)(obp + (wm + g + 8) * DIM + cb) =
            pack2(oacc[j][2] * inv1, oacc[j][3] * inv1);
    }
}

// merged attention: blocks [0,2048) local, [2048,4096) global
__global__ __launch_bounds__(256, 2) void attn_kernel() {
    int bx = blockIdx.x;
    if (bx < 2048) {
        int qt = bx & 3;
        int h = (bx >> 2) & 15;
        int w = (bx >> 6) & 7;
        int b = bx >> 9;
        const __half* base = g_xph + (b * SEQ + w * WINS) * DIM + h * HDIM;
        const __half* qb = base + (qt * 128) * DIM;
        __half* ob = g_local + (b * SEQ + w * WINS + qt * 128) * DIM + h * HDIM;
        flash_mma(qb, base, ob, 8);
    } else {
        bx -= 2048;
        int qt = bx & 31;
        int h = (bx >> 5) & 15;
        int b = bx >> 9;
        const __half* qb = g_xph + (b * SEQ + qt * 128) * DIM + h * HDIM;
        const __half* kb = g_gth + b * NGT * DIM + h * HDIM;
        __half* ob = g_glob + (b * SEQ + qt * 128) * DIM + h * HDIM;
        flash_mma(qb, kb, ob, 2);
    }
}

// ============== pipelined fp16 mma GEMM, 128x128 tile, KT=32 halves ==============
// (scalar-LDS fragments — the R9 configuration, which benchmarked fastest)
#define STG_H 10240
#define GP_SMEM (2 * STG_H * 2)

template <int MODE>
__device__ __forceinline__ void gp_load(__half* sm, int s, int m0, int n0, int k0,
                                        const __half* Bsrc, int tid) {
    __half* A = sm + s * STG_H;
    __half* B = A + 5120;
    constexpr int KTOT = (MODE == 0) ? 4096 : (MODE == 1) ? 2048 : 1024;
#pragma unroll
    for (int t = 0; t < 2; ++t) {
        int id = tid + t * 256;
        int r = id >> 2, q = id & 3;
        int kk = k0 + q * 8;
        const __half* src;
        if (MODE == 0) {
            int row = m0 + r;
            src = g_xph + ((row >> 6) * SEQ + (row & 63) * 4) * DIM + kk;
        } else if (MODE == 1) {
            src = (kk < 1024) ? g_local + (m0 + r) * 1024 + kk
                              : g_glob + (m0 + r) * 1024 + (kk - 1024);
        } else {
            src = g_mixed + (m0 + r) * 1024 + kk;
        }
        cp_async16(smem_u32(A + r * 40 + q * 8), src);
    }
#pragma unroll
    for (int t = 0; t < 2; ++t) {
        int id = tid + t * 256;
        int r = id >> 2, q = id & 3;
        cp_async16(smem_u32(B + r * 40 + q * 8), Bsrc + (n0 + r) * KTOT + k0 + q * 8);
    }
    cp_commit();
}

template <int MODE>
__global__ __launch_bounds__(256) void gemm_pipe(const float* __restrict__ bias,
                                                 float* __restrict__ Cext) {
    constexpr int NIT = (MODE == 0) ? 16 : (MODE == 1) ? 64 : 32;
    extern __shared__ __half smh[];
    const int tid = threadIdx.x;
    const int warp = tid >> 5, lane = tid & 31;
    const int g = lane >> 2, tg = lane & 3;
    const int wm = (warp >> 1) * 32, wn = (warp & 1) * 64;
    const int m0 = blockIdx.y * 128, n0 = blockIdx.x * 128;
    const int kbase = (MODE == 0) ? blockIdx.z * 512 : 0;
    const __half* Bsrc = (MODE == 0) ? g_cwT : (MODE == 1) ? g_gwT : g_owT;

    float acc[2][8][4];
#pragma unroll
    for (int mt = 0; mt < 2; ++mt)
#pragma unroll
        for (int j = 0; j < 8; ++j)
#pragma unroll
            for (int q = 0; q < 4; ++q) acc[mt][j][q] = 0.f;

    gp_load<MODE>(smh, 0, m0, n0, kbase, Bsrc, tid);

    for (int i = 0; i < NIT; ++i) {
        if (i + 1 < NIT) {
            gp_load<MODE>(smh, (i + 1) & 1, m0, n0, kbase + (i + 1) * 32, Bsrc, tid);
            asm volatile("cp.async.wait_group 1;" ::: "memory");
        } else {
            asm volatile("cp.async.wait_group 0;" ::: "memory");
        }
        __syncthreads();

        const __half* As = smh + (i & 1) * STG_H;
        const __half* Bs = As + 5120;
#pragma unroll
        for (int ks = 0; ks < 2; ++ks) {
            uint32_t bf[8][2];
#pragma unroll
            for (int j = 0; j < 8; ++j) {
                int n = wn + j * 8 + g;
                bf[j][0] = LDH32(Bs, n * 40 + ks * 16 + 2 * tg);
                bf[j][1] = LDH32(Bs, n * 40 + ks * 16 + 2 * tg + 8);
            }
#pragma unroll
            for (int mt = 0; mt < 2; ++mt) {
                int r0 = wm + mt * 16 + g;
                uint32_t a0 = LDH32(As, r0 * 40 + ks * 16 + 2 * tg);
                uint32_t a1 = LDH32(As, (r0 + 8) * 40 + ks * 16 + 2 * tg);
                uint32_t a2 = LDH32(As, r0 * 40 + ks * 16 + 2 * tg + 8);
                uint32_t a3 = LDH32(As, (r0 + 8) * 40 + ks * 16 + 2 * tg + 8);
#pragma unroll
                for (int j = 0; j < 8; ++j)
                    mma_f16(acc[mt][j], a0, a1, a2, a3, bf[j][0], bf[j][1]);
            }
        }
        __syncthreads();
    }

    // ---- epilogue ----
#pragma unroll
    for (int mt = 0; mt < 2; ++mt) {
#pragma unroll
        for (int j = 0; j < 8; ++j) {
            int col = n0 + wn + j * 8 + 2 * tg;
            int ra = m0 + wm + mt * 16 + g;
            int rb = ra + 8;
            if (MODE == 0) {
                atomicAdd(&g_comp[ra * 1024 + col], acc[mt][j][0]);
                atomicAdd(&g_comp[ra * 1024 + col + 1], acc[mt][j][1]);
                atomicAdd(&g_comp[rb * 1024 + col], acc[mt][j][2]);
                atomicAdd(&g_comp[rb * 1024 + col + 1], acc[mt][j][3]);
                continue;
            }
            float2 bz = *(const float2*)&bias[col];
            float z0x = acc[mt][j][0] + bz.x, z0y = acc[mt][j][1] + bz.y;
            float z1x = acc[mt][j][2] + bz.x, z1y = acc[mt][j][3] + bz.y;
            if (MODE == 1) {
                int ia = ra * 1024 + col, ib = rb * 1024 + col;
                float2 la = __half22float2(*(const __half2*)(g_local + ia));
                float2 lb = __half22float2(*(const __half2*)(g_local + ib));
                float2 ga = __half22float2(*(const __half2*)(g_glob + ia));
                float2 gb = __half22float2(*(const __half2*)(g_glob + ib));
                float s0x = 1.0f / (1.0f + fexp(-z0x));
                float s0y = 1.0f / (1.0f + fexp(-z0y));
                float s1x = 1.0f / (1.0f + fexp(-z1x));
                float s1y = 1.0f / (1.0f + fexp(-z1y));
                *(uint32_t*)(g_mixed + ia) =
                    pack2(s0x * la.x + (1.f - s0x) * ga.x,
                          s0y * la.y + (1.f - s0y) * ga.y);
                *(uint32_t*)(g_mixed + ib) =
                    pack2(s1x * lb.x + (1.f - s1x) * gb.x,
                          s1y * lb.y + (1.f - s1y) * gb.y);
            } else {
                *(float2*)&Cext[ra * 1024 + col] = make_float2(z0x, z0y);
                *(float2*)&Cext[rb * 1024 + col] = make_float2(z1x, z1y);
            }
        }
    }
}

// ---------------- launch ----------------
extern "C" void kernel_launch(void* const* d_in, const int* in_sizes, int n_in,
                              void* d_out, int out_size) {
    const float* x = (const float*)d_in[0];
    const float* pe = (const float*)d_in[1];
    const float* gm = (const float*)d_in[2];
    const float* cw = (const float*)d_in[3];
    const float* cb = (const float*)d_in[4];
    const float* gw = (const float*)d_in[5];
    const float* gb = (const float*)d_in[6];
    const float* ow = (const float*)d_in[7];
    const float* ob = (const float*)d_in[8];
    float* out = (float*)d_out;

    cudaFuncSetAttribute((const void*)attn_kernel,
                         cudaFuncAttributeMaxDynamicSharedMemorySize, 27648);
    cudaFuncSetAttribute((const void*)gemm_pipe<0>,
                         cudaFuncAttributeMaxDynamicSharedMemorySize, GP_SMEM);
    cudaFuncSetAttribute((const void*)gemm_pipe<1>,
                         cudaFuncAttributeMaxDynamicSharedMemorySize, GP_SMEM);
    cudaFuncSetAttribute((const void*)gemm_pipe<2>,
                         cudaFuncAttributeMaxDynamicSharedMemorySize, GP_SMEM);

    prep_kernel<<<PREP_END, 256>>>(x, pe, gw, ow, cw);
    gemm_pipe<0><<<dim3(8, 2, 8), 256, GP_SMEM>>>(nullptr, nullptr);  // conv split-K
    scatter_gt_kernel<<<512, 256>>>(cb, gm);
    attn_kernel<<<4096, 256, 27648>>>();
    gemm_pipe<1><<<dim3(8, 128), 256, GP_SMEM>>>(gb, nullptr);  // gate + mix
    gemm_pipe<2><<<dim3(8, 128), 256, GP_SMEM>>>(ob, out);      // output projection
}